// round 15
// baseline (speedup 1.0000x reference)
#include <cuda_runtime.h>
#include <cuda_fp16.h>
#include <math.h>
#include <stdint.h>

#define NN   100000
#define NE   3200000
#define FIN  512
#define CD   64
#define KORD 10
#define NBLK 98              // ceil(NN / 1024)

// ---- static scratch (no device allocations allowed) ----
__device__ int    g_idx64;                 // 1 if edge_index is int64, 0 if int32
__device__ int    g_deg[NN];
__device__ int    g_off[NN + 1];
__device__ int    g_cur[NN];
__device__ int    g_bsum[NBLK];
__device__ float  g_dinv[NN];              // rsqrt(deg) or 1
__device__ float  g_dinv2[NN];             // dinv^2
__device__ float  g_isq[NN];               // sqrt(deg) or 1
__device__ int    g_src[NE];               // CSR by dst: source index only
// Q_n = dinv ⊙ P_n, fp16 storage, ping-pong. Row = 64 half = 128 B.
__device__ half2  g_Qa[(size_t)NN * 32];
__device__ half2  g_Qb[(size_t)NN * 32];
__device__ float  g_ret[(size_t)NN * CD];  // Σ coef_n · mf_n ⊙ Q_n (Q-space, fp32)

// ---------------- probe + zero (merged) ----------------
__global__ void k_probe_zero(const void* ei) {
    int i = blockIdx.x * blockDim.x + threadIdx.x;
    if (i < NN) g_deg[i] = 0;
    if (i == 0) {
        const long long* p = (const long long*)ei;
        int ok = 1;
        for (int j = 0; j < 256; j++) {
            long long v = p[j];
            if (v < 0 || v >= NN) { ok = 0; break; }
        }
        g_idx64 = ok;
    }
}

__device__ __forceinline__ int load_idx(const void* ei, long long i, int is64) {
    if (is64) return (int)((const long long*)ei)[i];
    return ((const int*)ei)[i];
}

// ---------------- setup ----------------
__global__ void k_deg(const void* __restrict__ ei) {
    int t = blockIdx.x * blockDim.x + threadIdx.x;
    int is64 = g_idx64;
    int e = t * 2;
    if (e < NE) {
        int c0 = load_idx(ei, (long long)NE + e, is64);
        int c1 = load_idx(ei, (long long)NE + e + 1, is64);
        atomicAdd(&g_deg[c0], 1);
        atomicAdd(&g_deg[c1], 1);
    }
}

__global__ void k_dinv() {
    int i = blockIdx.x * blockDim.x + threadIdx.x;
    if (i < NN) {
        int d = g_deg[i];
        if (d > 0) {
            float r = rsqrtf((float)d);
            g_dinv[i]  = r;
            g_dinv2[i] = r * r;
            g_isq[i]   = sqrtf((float)d);
        } else {
            g_dinv[i] = 1.0f; g_dinv2[i] = 1.0f; g_isq[i] = 1.0f;
        }
    }
}

// -------- multi-block scan: phase 1 — block-local exclusive scan + block totals --------
__global__ void __launch_bounds__(1024) k_scan1() {
    __shared__ int wsum[32];
    int tid = threadIdx.x, lane = tid & 31, wid = tid >> 5;
    int i = blockIdx.x * 1024 + tid;
    int v = (i < NN) ? g_deg[i] : 0;
    int x = v;
    #pragma unroll
    for (int d = 1; d < 32; d <<= 1) {
        int y = __shfl_up_sync(0xffffffffu, x, d);
        if (lane >= d) x += y;
    }
    if (lane == 31) wsum[wid] = x;
    __syncthreads();
    if (wid == 0) {
        int t = wsum[lane];
        #pragma unroll
        for (int d = 1; d < 32; d <<= 1) {
            int y = __shfl_up_sync(0xffffffffu, t, d);
            if (lane >= d) t += y;
        }
        wsum[lane] = t;
    }
    __syncthreads();
    int excl = (wid ? wsum[wid - 1] : 0) + (x - v);
    if (i < NN) g_off[i] = excl;
    if (tid == 0) g_bsum[blockIdx.x] = wsum[31];
}

// -------- phase 2 — exclusive scan of 98 block totals (one 128-thread block) --------
__global__ void k_scan2() {
    __shared__ int wsum[4];
    int tid = threadIdx.x, lane = tid & 31, wid = tid >> 5;
    int v = (tid < NBLK) ? g_bsum[tid] : 0;
    int x = v;
    #pragma unroll
    for (int d = 1; d < 32; d <<= 1) {
        int y = __shfl_up_sync(0xffffffffu, x, d);
        if (lane >= d) x += y;
    }
    if (lane == 31) wsum[wid] = x;
    __syncthreads();
    if (tid == 0) {
        int run = 0;
        #pragma unroll
        for (int w = 0; w < 4; w++) { int t = wsum[w]; wsum[w] = run; run += t; }
        g_off[NN] = run;
    }
    __syncthreads();
    int excl = wsum[wid] + (x - v);
    if (tid < NBLK) g_bsum[tid] = excl;
}

// -------- phase 3 — add block offsets, fill g_cur --------
__global__ void k_scan3() {
    int i = blockIdx.x * blockDim.x + threadIdx.x;
    if (i < NN) {
        int o = g_off[i] + g_bsum[i >> 10];
        g_off[i] = o;
        g_cur[i] = o;
    }
}

__global__ void k_scatter(const void* __restrict__ ei) {
    int e = blockIdx.x * blockDim.x + threadIdx.x;
    int is64 = g_idx64;
    if (e < NE) {
        int r = load_idx(ei, e, is64);
        int c = load_idx(ei, (long long)NE + e, is64);
        int pos = atomicAdd(&g_cur[c], 1);
        g_src[pos] = r;
    }
}

// ---------------- tensor-core GEMM helpers ----------------
__device__ __forceinline__ uint32_t smem_u32(const void* p) {
    return (uint32_t)__cvta_generic_to_shared(p);
}
__device__ __forceinline__ void ldsm_x4(uint32_t& r0, uint32_t& r1,
                                        uint32_t& r2, uint32_t& r3, uint32_t a) {
    asm volatile("ldmatrix.sync.aligned.m8n8.x4.shared.b16 {%0,%1,%2,%3}, [%4];"
                 : "=r"(r0), "=r"(r1), "=r"(r2), "=r"(r3) : "r"(a));
}
__device__ __forceinline__ void ldsm_x4_t(uint32_t& r0, uint32_t& r1,
                                          uint32_t& r2, uint32_t& r3, uint32_t a) {
    asm volatile("ldmatrix.sync.aligned.m8n8.x4.trans.shared.b16 {%0,%1,%2,%3}, [%4];"
                 : "=r"(r0), "=r"(r1), "=r"(r2), "=r"(r3) : "r"(a));
}
__device__ __forceinline__ void mma16816(float* c, const uint32_t* a,
                                         uint32_t b0, uint32_t b1) {
    asm volatile(
        "mma.sync.aligned.m16n8k16.row.col.f32.f16.f16.f32 "
        "{%0,%1,%2,%3}, {%4,%5,%6,%7}, {%8,%9}, {%0,%1,%2,%3};"
        : "+f"(c[0]), "+f"(c[1]), "+f"(c[2]), "+f"(c[3])
        : "r"(a[0]), "r"(a[1]), "r"(a[2]), "r"(a[3]), "r"(b0), "r"(b1));
}

// -------- GEMM (HMMA, double-buffered): h = x@W + b ; Q0 = dinv⊙h ; ret = mf0⊙Q0 --------
// 128x64 block tile, 8 warps (4M x 2N), K-step 32, register-staged LDG -> STS,
// ping-pong smem buffers, one __syncthreads per k-iteration.
#define APAD 40
#define BPAD 72
__global__ void __launch_bounds__(256) k_gemm_tc(const float* __restrict__ X,
                                                 const float* __restrict__ W,
                                                 const float* __restrict__ bias,
                                                 const float* __restrict__ mf0) {
    __shared__ half Ah[2][128][APAD];
    __shared__ half Bh[2][32][BPAD];
    int tid  = threadIdx.x;
    int lane = tid & 31;
    int wid  = tid >> 5;
    int warp_m = wid & 3;
    int warp_n = wid >> 2;
    int rowBase = blockIdx.x * 128;

    float acc[2][4][4];
    #pragma unroll
    for (int mi = 0; mi < 2; mi++)
        #pragma unroll
        for (int ni = 0; ni < 4; ni++)
            #pragma unroll
            for (int j = 0; j < 4; j++) acc[mi][ni][j] = 0.f;

    int lmat = lane >> 3, lrow = lane & 7;

    // per-thread load coordinates (fixed across iterations)
    int ar[4], ac[4];
    #pragma unroll
    for (int i = 0; i < 4; i++) {
        int f = tid * 4 + i;
        ar[i] = f >> 3;
        ac[i] = (f & 7) * 4;
    }
    int br[2], bc[2];
    #pragma unroll
    for (int i = 0; i < 2; i++) {
        int f = tid * 2 + i;
        br[i] = f >> 4;
        bc[i] = (f & 15) * 4;
    }

    float4 ra[4], rb[2];
    // prefetch tile 0
    #pragma unroll
    for (int i = 0; i < 4; i++) {
        int rr = rowBase + ar[i];
        if (rr >= NN) rr = NN - 1;
        ra[i] = *(const float4*)&X[(size_t)rr * FIN + ac[i]];
    }
    #pragma unroll
    for (int i = 0; i < 2; i++)
        rb[i] = *(const float4*)&W[(size_t)br[i] * CD + bc[i]];
    // store tile 0 -> buffer 0
    #pragma unroll
    for (int i = 0; i < 4; i++) {
        half2* dst = (half2*)&Ah[0][ar[i]][ac[i]];
        dst[0] = __floats2half2_rn(ra[i].x, ra[i].y);
        dst[1] = __floats2half2_rn(ra[i].z, ra[i].w);
    }
    #pragma unroll
    for (int i = 0; i < 2; i++) {
        half2* dst = (half2*)&Bh[0][br[i]][bc[i]];
        dst[0] = __floats2half2_rn(rb[i].x, rb[i].y);
        dst[1] = __floats2half2_rn(rb[i].z, rb[i].w);
    }
    __syncthreads();

    #pragma unroll
    for (int it = 0; it < FIN / 32; it++) {
        int cur = it & 1;
        int k0n = (it + 1) * 32;
        if (it < FIN / 32 - 1) {
            #pragma unroll
            for (int i = 0; i < 4; i++) {
                int rr = rowBase + ar[i];
                if (rr >= NN) rr = NN - 1;
                ra[i] = *(const float4*)&X[(size_t)rr * FIN + k0n + ac[i]];
            }
            #pragma unroll
            for (int i = 0; i < 2; i++)
                rb[i] = *(const float4*)&W[(size_t)(k0n + br[i]) * CD + bc[i]];
        }
        // compute on buffer cur
        #pragma unroll
        for (int kk = 0; kk < 32; kk += 16) {
            uint32_t a[2][4];
            #pragma unroll
            for (int mi = 0; mi < 2; mi++) {
                int row = warp_m * 32 + mi * 16 + (lmat & 1) * 8 + lrow;
                int col = kk + (lmat >> 1) * 8;
                ldsm_x4(a[mi][0], a[mi][1], a[mi][2], a[mi][3],
                        smem_u32(&Ah[cur][row][col]));
            }
            uint32_t b[4][2];
            #pragma unroll
            for (int nc = 0; nc < 2; nc++) {
                int krow = kk + (lmat & 1) * 8 + lrow;
                int ncol = warp_n * 32 + nc * 16 + (lmat >> 1) * 8;
                uint32_t r0, r1, r2, r3;
                ldsm_x4_t(r0, r1, r2, r3, smem_u32(&Bh[cur][krow][ncol]));
                b[nc * 2 + 0][0] = r0; b[nc * 2 + 0][1] = r1;
                b[nc * 2 + 1][0] = r2; b[nc * 2 + 1][1] = r3;
            }
            #pragma unroll
            for (int mi = 0; mi < 2; mi++)
                #pragma unroll
                for (int ni = 0; ni < 4; ni++)
                    mma16816(acc[mi][ni], a[mi], b[ni][0], b[ni][1]);
        }
        if (it < FIN / 32 - 1) {
            int nxt = cur ^ 1;
            #pragma unroll
            for (int i = 0; i < 4; i++) {
                half2* dst = (half2*)&Ah[nxt][ar[i]][ac[i]];
                dst[0] = __floats2half2_rn(ra[i].x, ra[i].y);
                dst[1] = __floats2half2_rn(ra[i].z, ra[i].w);
            }
            #pragma unroll
            for (int i = 0; i < 2; i++) {
                half2* dst = (half2*)&Bh[nxt][br[i]][bc[i]];
                dst[0] = __floats2half2_rn(rb[i].x, rb[i].y);
                dst[1] = __floats2half2_rn(rb[i].z, rb[i].w);
            }
            __syncthreads();
        }
    }

    int groupr = lane >> 2;
    int coff   = (lane & 3) * 2;
    int rwbase = rowBase + warp_m * 32;
    int cbase  = warp_n * 32;
    #pragma unroll
    for (int ni = 0; ni < 4; ni++) {
        int col = cbase + ni * 8 + coff;
        float b0 = bias[col], b1 = bias[col + 1];
        float m0 = mf0[col],  m1 = mf0[col + 1];
        #pragma unroll
        for (int mi = 0; mi < 2; mi++) {
            #pragma unroll
            for (int half_row = 0; half_row < 2; half_row++) {
                int row = rwbase + mi * 16 + half_row * 8 + groupr;
                if (row < NN) {
                    float dv = g_dinv[row];
                    float q0 = dv * (acc[mi][ni][half_row * 2 + 0] + b0);
                    float q1 = dv * (acc[mi][ni][half_row * 2 + 1] + b1);
                    g_ret[(size_t)row * CD + col]     = q0 * m0;
                    g_ret[(size_t)row * CD + col + 1] = q1 * m1;
                    g_Qa[(size_t)row * 32 + (col >> 1)] = __floats2half2_rn(q0, q1);
                }
            }
        }
    }
}

// -------- prop: Q_n = (2-[n==1])*dinv2[i]*Σ_e Q_{n-1}[src] - [n>1]*Q_{n-2} --------
// fused: ret += coef_n * mf_n ⊙ Q_n (pre-quantization fp32 value)
// warp per node, 2 edges in flight: lanes 0-15 -> edge e, 16-31 -> edge e+1.
__global__ void __launch_bounds__(256) k_prop(int n, const float* __restrict__ lap,
                                              const float* __restrict__ mfw) {
    int gw   = (blockIdx.x * blockDim.x + threadIdx.x) >> 5;
    int lane = threadIdx.x & 31;
    if (gw >= NN) return;
    int hf  = lane >> 4;          // 0 or 1
    int sub = lane & 15;          // channel group: 4 channels at sub*4
    const half* __restrict__ Qprev = (const half*)((n & 1) ? g_Qa : g_Qb);
    half* __restrict__ Qout        = (half*)((n & 1) ? g_Qb : g_Qa);

    int beg = g_off[gw], end = g_off[gw + 1];
    float a0 = 0.f, a1 = 0.f, a2 = 0.f, a3 = 0.f;
    float c0 = 0.f, c1 = 0.f, c2 = 0.f, c3 = 0.f;
    int e = beg;
    for (; e + 8 <= end; e += 8) {
        int s0 = g_src[e + hf];
        int s1 = g_src[e + 2 + hf];
        int s2 = g_src[e + 4 + hf];
        int s3 = g_src[e + 6 + hf];
        uint2 u0 = *(const uint2*)(Qprev + (size_t)s0 * 64 + sub * 4);
        uint2 u1 = *(const uint2*)(Qprev + (size_t)s1 * 64 + sub * 4);
        uint2 u2 = *(const uint2*)(Qprev + (size_t)s2 * 64 + sub * 4);
        uint2 u3 = *(const uint2*)(Qprev + (size_t)s3 * 64 + sub * 4);
        float2 p, q;
        p = __half22float2(*(half2*)&u0.x); q = __half22float2(*(half2*)&u0.y);
        a0 += p.x; a1 += p.y; a2 += q.x; a3 += q.y;
        p = __half22float2(*(half2*)&u1.x); q = __half22float2(*(half2*)&u1.y);
        c0 += p.x; c1 += p.y; c2 += q.x; c3 += q.y;
        p = __half22float2(*(half2*)&u2.x); q = __half22float2(*(half2*)&u2.y);
        a0 += p.x; a1 += p.y; a2 += q.x; a3 += q.y;
        p = __half22float2(*(half2*)&u3.x); q = __half22float2(*(half2*)&u3.y);
        c0 += p.x; c1 += p.y; c2 += q.x; c3 += q.y;
    }
    for (; e + 2 <= end; e += 2) {
        int s = g_src[e + hf];
        uint2 u = *(const uint2*)(Qprev + (size_t)s * 64 + sub * 4);
        float2 p = __half22float2(*(half2*)&u.x);
        float2 q = __half22float2(*(half2*)&u.y);
        a0 += p.x; a1 += p.y; a2 += q.x; a3 += q.y;
    }
    if (e < end && hf == 0) {
        int s = g_src[e];
        uint2 u = *(const uint2*)(Qprev + (size_t)s * 64 + sub * 4);
        float2 p = __half22float2(*(half2*)&u.x);
        float2 q = __half22float2(*(half2*)&u.y);
        a0 += p.x; a1 += p.y; a2 += q.x; a3 += q.y;
    }
    a0 += c0; a1 += c1; a2 += c2; a3 += c3;
    a0 += __shfl_down_sync(0xffffffffu, a0, 16);
    a1 += __shfl_down_sync(0xffffffffu, a1, 16);
    a2 += __shfl_down_sync(0xffffffffu, a2, 16);
    a3 += __shfl_down_sync(0xffffffffu, a3, 16);

    if (hf == 0) {
        size_t base = (size_t)gw * 64 + sub * 4;
        float d2 = g_dinv2[gw];
        float q0, q1, q2, q3;
        if (n == 1) {
            q0 = d2 * a0; q1 = d2 * a1; q2 = d2 * a2; q3 = d2 * a3;
        } else {
            uint2 oldu = *(const uint2*)(Qout + base);   // holds Q_{n-2}
            float2 o0 = __half22float2(*(half2*)&oldu.x);
            float2 o1 = __half22float2(*(half2*)&oldu.y);
            float s2x = 2.0f * d2;
            q0 = fmaf(s2x, a0, -o0.x);
            q1 = fmaf(s2x, a1, -o0.y);
            q2 = fmaf(s2x, a2, -o1.x);
            q3 = fmaf(s2x, a3, -o1.y);
        }
        uint2 outw;
        *(half2*)&outw.x = __floats2half2_rn(q0, q1);
        *(half2*)&outw.y = __floats2half2_rn(q2, q3);
        *(uint2*)(Qout + base) = outw;

        float coef = __ldg(&lap[n - 1]);
        float4 mfv = *(const float4*)(mfw + (size_t)n * CD + sub * 4);
        float4 r = *(float4*)(g_ret + base);
        r.x = fmaf(coef * mfv.x, q0, r.x);
        r.y = fmaf(coef * mfv.y, q1, r.y);
        r.z = fmaf(coef * mfv.z, q2, r.z);
        r.w = fmaf(coef * mfv.w, q3, r.w);
        *(float4*)(g_ret + base) = r;
    }
}

// -------- final: ret *= isq ; log_softmax --------
__global__ void __launch_bounds__(256) k_final(float* __restrict__ out) {
    int gw   = (blockIdx.x * blockDim.x + threadIdx.x) >> 5;
    int lane = threadIdx.x & 31;
    if (gw >= NN) return;
    size_t idx = (size_t)gw * 32 + lane;
    float isq = g_isq[gw];
    float2 v = ((const float2*)g_ret)[idx];
    float rx = v.x * isq, ry = v.y * isq;

    float m = fmaxf(rx, ry);
    #pragma unroll
    for (int d = 16; d > 0; d >>= 1)
        m = fmaxf(m, __shfl_xor_sync(0xffffffffu, m, d));
    float s = expf(rx - m) + expf(ry - m);
    #pragma unroll
    for (int d = 16; d > 0; d >>= 1)
        s += __shfl_xor_sync(0xffffffffu, s, d);
    float lse = m + logf(s);
    ((float2*)out)[idx] = make_float2(rx - lse, ry - lse);
}

// ---------------- launch ----------------
extern "C" void kernel_launch(void* const* d_in, const int* in_sizes, int n_in,
                              void* d_out, int out_size) {
    const float* x   = (const float*)d_in[0];
    const void*  ei  = d_in[1];
    const float* W   = (const float*)d_in[2];
    const float* b   = (const float*)d_in[3];
    const float* lap = (const float*)d_in[4];
    const float* mf  = (const float*)d_in[5];
    float*       out = (float*)d_out;

    k_probe_zero<<<(NN + 255) / 256, 256>>>(ei);
    k_deg<<<(NE / 2 + 255) / 256, 256>>>(ei);
    k_dinv<<<(NN + 255) / 256, 256>>>();
    k_scan1<<<NBLK, 1024>>>();
    k_scan2<<<1, 128>>>();
    k_scan3<<<(NN + 255) / 256, 256>>>();
    k_scatter<<<NE / 256, 256>>>(ei);
    k_gemm_tc<<<(NN + 127) / 128, 256>>>(x, W, b, mf);
    for (int n = 1; n <= KORD; n++)
        k_prop<<<(NN * 32) / 256, 256>>>(n, lap, mf);
    k_final<<<(NN * 32) / 256, 256>>>(out);
}

// round 16
// speedup vs baseline: 1.0131x; 1.0131x over previous
#include <cuda_runtime.h>
#include <cuda_fp16.h>
#include <math.h>
#include <stdint.h>

#define NN   100000
#define NE   3200000
#define FIN  512
#define CD   64
#define KORD 10
#define NBLK 98              // ceil(NN / 1024)

// ---- static scratch (no device allocations allowed) ----
__device__ int    g_idx64;                 // 1 if edge_index is int64, 0 if int32
__device__ int    g_deg[NN];
__device__ int    g_off[NN + 1];
__device__ int    g_cur[NN];
__device__ int    g_bsum[NBLK];
__device__ float  g_dinv[NN];              // rsqrt(deg) or 1
__device__ float  g_dinv2[NN];             // dinv^2
__device__ float  g_isq[NN];               // sqrt(deg) or 1
__device__ int    g_src[NE];               // CSR by dst: source index only
// Q_n = dinv ⊙ P_n, fp16 storage, ping-pong. Row = 64 half = 128 B.
__device__ half2  g_Qa[(size_t)NN * 32];
__device__ half2  g_Qb[(size_t)NN * 32];
__device__ float  g_ret[(size_t)NN * CD];  // Σ coef_n · mf_n ⊙ Q_n (Q-space, fp32)

// ---------------- probe + zero (merged) ----------------
__global__ void k_probe_zero(const void* ei) {
    int i = blockIdx.x * blockDim.x + threadIdx.x;
    if (i < NN) g_deg[i] = 0;
    if (i == 0) {
        const long long* p = (const long long*)ei;
        int ok = 1;
        for (int j = 0; j < 256; j++) {
            long long v = p[j];
            if (v < 0 || v >= NN) { ok = 0; break; }
        }
        g_idx64 = ok;
    }
}

__device__ __forceinline__ int load_idx(const void* ei, long long i, int is64) {
    if (is64) return (int)((const long long*)ei)[i];
    return ((const int*)ei)[i];
}

// ---------------- setup ----------------
__global__ void k_deg(const void* __restrict__ ei) {
    int t = blockIdx.x * blockDim.x + threadIdx.x;
    int is64 = g_idx64;
    int e = t * 2;
    if (e < NE) {
        int c0 = load_idx(ei, (long long)NE + e, is64);
        int c1 = load_idx(ei, (long long)NE + e + 1, is64);
        atomicAdd(&g_deg[c0], 1);
        atomicAdd(&g_deg[c1], 1);
    }
}

// -------- scan phase 1 (fused with dinv/dinv2/isq) --------
__global__ void __launch_bounds__(1024) k_scan1() {
    __shared__ int wsum[32];
    int tid = threadIdx.x, lane = tid & 31, wid = tid >> 5;
    int i = blockIdx.x * 1024 + tid;
    int v = (i < NN) ? g_deg[i] : 0;
    // fused dinv computation
    if (i < NN) {
        if (v > 0) {
            float r = rsqrtf((float)v);
            g_dinv[i]  = r;
            g_dinv2[i] = r * r;
            g_isq[i]   = sqrtf((float)v);
        } else {
            g_dinv[i] = 1.0f; g_dinv2[i] = 1.0f; g_isq[i] = 1.0f;
        }
    }
    int x = v;
    #pragma unroll
    for (int d = 1; d < 32; d <<= 1) {
        int y = __shfl_up_sync(0xffffffffu, x, d);
        if (lane >= d) x += y;
    }
    if (lane == 31) wsum[wid] = x;
    __syncthreads();
    if (wid == 0) {
        int t = wsum[lane];
        #pragma unroll
        for (int d = 1; d < 32; d <<= 1) {
            int y = __shfl_up_sync(0xffffffffu, t, d);
            if (lane >= d) t += y;
        }
        wsum[lane] = t;
    }
    __syncthreads();
    int excl = (wid ? wsum[wid - 1] : 0) + (x - v);
    if (i < NN) g_off[i] = excl;
    if (tid == 0) g_bsum[blockIdx.x] = wsum[31];
}

// -------- phase 2 — exclusive scan of 98 block totals --------
__global__ void k_scan2() {
    __shared__ int wsum[4];
    int tid = threadIdx.x, lane = tid & 31, wid = tid >> 5;
    int v = (tid < NBLK) ? g_bsum[tid] : 0;
    int x = v;
    #pragma unroll
    for (int d = 1; d < 32; d <<= 1) {
        int y = __shfl_up_sync(0xffffffffu, x, d);
        if (lane >= d) x += y;
    }
    if (lane == 31) wsum[wid] = x;
    __syncthreads();
    if (tid == 0) {
        int run = 0;
        #pragma unroll
        for (int w = 0; w < 4; w++) { int t = wsum[w]; wsum[w] = run; run += t; }
        g_off[NN] = run;
    }
    __syncthreads();
    int excl = wsum[wid] + (x - v);
    if (tid < NBLK) g_bsum[tid] = excl;
}

// -------- phase 3 — add block offsets, fill g_cur --------
__global__ void k_scan3() {
    int i = blockIdx.x * blockDim.x + threadIdx.x;
    if (i < NN) {
        int o = g_off[i] + g_bsum[i >> 10];
        g_off[i] = o;
        g_cur[i] = o;
    }
}

__global__ void k_scatter(const void* __restrict__ ei) {
    int e = blockIdx.x * blockDim.x + threadIdx.x;
    int is64 = g_idx64;
    if (e < NE) {
        int r = load_idx(ei, e, is64);
        int c = load_idx(ei, (long long)NE + e, is64);
        int pos = atomicAdd(&g_cur[c], 1);
        g_src[pos] = r;
    }
}

// ---------------- tensor-core GEMM helpers ----------------
__device__ __forceinline__ uint32_t smem_u32(const void* p) {
    return (uint32_t)__cvta_generic_to_shared(p);
}
__device__ __forceinline__ void ldsm_x4(uint32_t& r0, uint32_t& r1,
                                        uint32_t& r2, uint32_t& r3, uint32_t a) {
    asm volatile("ldmatrix.sync.aligned.m8n8.x4.shared.b16 {%0,%1,%2,%3}, [%4];"
                 : "=r"(r0), "=r"(r1), "=r"(r2), "=r"(r3) : "r"(a));
}
__device__ __forceinline__ void ldsm_x4_t(uint32_t& r0, uint32_t& r1,
                                          uint32_t& r2, uint32_t& r3, uint32_t a) {
    asm volatile("ldmatrix.sync.aligned.m8n8.x4.trans.shared.b16 {%0,%1,%2,%3}, [%4];"
                 : "=r"(r0), "=r"(r1), "=r"(r2), "=r"(r3) : "r"(a));
}
__device__ __forceinline__ void mma16816(float* c, const uint32_t* a,
                                         uint32_t b0, uint32_t b1) {
    asm volatile(
        "mma.sync.aligned.m16n8k16.row.col.f32.f16.f16.f32 "
        "{%0,%1,%2,%3}, {%4,%5,%6,%7}, {%8,%9}, {%0,%1,%2,%3};"
        : "+f"(c[0]), "+f"(c[1]), "+f"(c[2]), "+f"(c[3])
        : "r"(a[0]), "r"(a[1]), "r"(a[2]), "r"(a[3]), "r"(b0), "r"(b1));
}

// -------- GEMM (HMMA): h = x@W + b ; Q0 = dinv⊙h (fp16) ; ret = mf0 ⊙ Q0 (fp32) --------
#define APAD 40
#define BPAD 72
__global__ void __launch_bounds__(256) k_gemm_tc(const float* __restrict__ X,
                                                 const float* __restrict__ W,
                                                 const float* __restrict__ bias,
                                                 const float* __restrict__ mf0) {
    __shared__ half Ah[128][APAD];
    __shared__ half Bh[32][BPAD];
    int tid  = threadIdx.x;
    int lane = tid & 31;
    int wid  = tid >> 5;
    int warp_m = wid & 3;
    int warp_n = wid >> 2;
    int rowBase = blockIdx.x * 128;

    float acc[2][4][4];
    #pragma unroll
    for (int mi = 0; mi < 2; mi++)
        #pragma unroll
        for (int ni = 0; ni < 4; ni++)
            #pragma unroll
            for (int j = 0; j < 4; j++) acc[mi][ni][j] = 0.f;

    int lmat = lane >> 3, lrow = lane & 7;

    for (int k0 = 0; k0 < FIN; k0 += 32) {
        #pragma unroll
        for (int i = 0; i < 4; i++) {
            int f = tid * 4 + i;
            int r = f >> 3;
            int sg = (f & 7) * 4;
            int rr = rowBase + r;
            if (rr >= NN) rr = NN - 1;
            float4 v = *(const float4*)&X[(size_t)rr * FIN + k0 + sg];
            half2* dst = (half2*)&Ah[r][sg];
            dst[0] = __floats2half2_rn(v.x, v.y);
            dst[1] = __floats2half2_rn(v.z, v.w);
        }
        #pragma unroll
        for (int i = 0; i < 2; i++) {
            int f = tid * 2 + i;
            int rk = f >> 4;
            int sg = (f & 15) * 4;
            float4 v = *(const float4*)&W[(size_t)(k0 + rk) * CD + sg];
            half2* dst = (half2*)&Bh[rk][sg];
            dst[0] = __floats2half2_rn(v.x, v.y);
            dst[1] = __floats2half2_rn(v.z, v.w);
        }
        __syncthreads();
        #pragma unroll
        for (int kk = 0; kk < 32; kk += 16) {
            uint32_t a[2][4];
            #pragma unroll
            for (int mi = 0; mi < 2; mi++) {
                int row = warp_m * 32 + mi * 16 + (lmat & 1) * 8 + lrow;
                int col = kk + (lmat >> 1) * 8;
                ldsm_x4(a[mi][0], a[mi][1], a[mi][2], a[mi][3],
                        smem_u32(&Ah[row][col]));
            }
            uint32_t b[4][2];
            #pragma unroll
            for (int nc = 0; nc < 2; nc++) {
                int krow = kk + (lmat & 1) * 8 + lrow;
                int ncol = warp_n * 32 + nc * 16 + (lmat >> 1) * 8;
                uint32_t r0, r1, r2, r3;
                ldsm_x4_t(r0, r1, r2, r3, smem_u32(&Bh[krow][ncol]));
                b[nc * 2 + 0][0] = r0; b[nc * 2 + 0][1] = r1;
                b[nc * 2 + 1][0] = r2; b[nc * 2 + 1][1] = r3;
            }
            #pragma unroll
            for (int mi = 0; mi < 2; mi++)
                #pragma unroll
                for (int ni = 0; ni < 4; ni++)
                    mma16816(acc[mi][ni], a[mi], b[ni][0], b[ni][1]);
        }
        __syncthreads();
    }

    int groupr = lane >> 2;
    int coff   = (lane & 3) * 2;
    int rwbase = rowBase + warp_m * 32;
    int cbase  = warp_n * 32;
    #pragma unroll
    for (int ni = 0; ni < 4; ni++) {
        int col = cbase + ni * 8 + coff;
        float b0 = bias[col], b1 = bias[col + 1];
        float m0 = mf0[col],  m1 = mf0[col + 1];
        #pragma unroll
        for (int mi = 0; mi < 2; mi++) {
            #pragma unroll
            for (int half_row = 0; half_row < 2; half_row++) {
                int row = rwbase + mi * 16 + half_row * 8 + groupr;
                if (row < NN) {
                    float dv = g_dinv[row];
                    float q0 = dv * (acc[mi][ni][half_row * 2 + 0] + b0);
                    float q1 = dv * (acc[mi][ni][half_row * 2 + 1] + b1);
                    g_ret[(size_t)row * CD + col]     = q0 * m0;
                    g_ret[(size_t)row * CD + col + 1] = q1 * m1;
                    g_Qa[(size_t)row * 32 + (col >> 1)] = __floats2half2_rn(q0, q1);
                }
            }
        }
    }
}

// -------- prop: Q_n = (2-[n==1])*dinv2[i]*Σ_e Q_{n-1}[src] - [n>1]*Q_{n-2} --------
// fused: ret += coef_n * mf_n ⊙ Q_n. LAST=1 (n==KORD): also isq-scale + log_softmax
// directly to out (skips Qout store and ret write-back).
template <int LAST>
__global__ void __launch_bounds__(256) k_prop(int n, const float* __restrict__ lap,
                                              const float* __restrict__ mfw,
                                              float* __restrict__ out) {
    int gw   = (blockIdx.x * blockDim.x + threadIdx.x) >> 5;
    int lane = threadIdx.x & 31;
    if (gw >= NN) return;
    int hf  = lane >> 4;          // 0 or 1
    int sub = lane & 15;          // channel group: 4 channels at sub*4
    const half* __restrict__ Qprev = (const half*)((n & 1) ? g_Qa : g_Qb);
    half* __restrict__ Qout        = (half*)((n & 1) ? g_Qb : g_Qa);

    int beg = g_off[gw], end = g_off[gw + 1];
    float a0 = 0.f, a1 = 0.f, a2 = 0.f, a3 = 0.f;
    float c0 = 0.f, c1 = 0.f, c2 = 0.f, c3 = 0.f;
    int e = beg;
    for (; e + 8 <= end; e += 8) {
        int s0 = g_src[e + hf];
        int s1 = g_src[e + 2 + hf];
        int s2 = g_src[e + 4 + hf];
        int s3 = g_src[e + 6 + hf];
        uint2 u0 = *(const uint2*)(Qprev + (size_t)s0 * 64 + sub * 4);
        uint2 u1 = *(const uint2*)(Qprev + (size_t)s1 * 64 + sub * 4);
        uint2 u2 = *(const uint2*)(Qprev + (size_t)s2 * 64 + sub * 4);
        uint2 u3 = *(const uint2*)(Qprev + (size_t)s3 * 64 + sub * 4);
        float2 p, q;
        p = __half22float2(*(half2*)&u0.x); q = __half22float2(*(half2*)&u0.y);
        a0 += p.x; a1 += p.y; a2 += q.x; a3 += q.y;
        p = __half22float2(*(half2*)&u1.x); q = __half22float2(*(half2*)&u1.y);
        c0 += p.x; c1 += p.y; c2 += q.x; c3 += q.y;
        p = __half22float2(*(half2*)&u2.x); q = __half22float2(*(half2*)&u2.y);
        a0 += p.x; a1 += p.y; a2 += q.x; a3 += q.y;
        p = __half22float2(*(half2*)&u3.x); q = __half22float2(*(half2*)&u3.y);
        c0 += p.x; c1 += p.y; c2 += q.x; c3 += q.y;
    }
    for (; e + 2 <= end; e += 2) {
        int s = g_src[e + hf];
        uint2 u = *(const uint2*)(Qprev + (size_t)s * 64 + sub * 4);
        float2 p = __half22float2(*(half2*)&u.x);
        float2 q = __half22float2(*(half2*)&u.y);
        a0 += p.x; a1 += p.y; a2 += q.x; a3 += q.y;
    }
    if (e < end && hf == 0) {
        int s = g_src[e];
        uint2 u = *(const uint2*)(Qprev + (size_t)s * 64 + sub * 4);
        float2 p = __half22float2(*(half2*)&u.x);
        float2 q = __half22float2(*(half2*)&u.y);
        a0 += p.x; a1 += p.y; a2 += q.x; a3 += q.y;
    }
    a0 += c0; a1 += c1; a2 += c2; a3 += c3;
    a0 += __shfl_down_sync(0xffffffffu, a0, 16);
    a1 += __shfl_down_sync(0xffffffffu, a1, 16);
    a2 += __shfl_down_sync(0xffffffffu, a2, 16);
    a3 += __shfl_down_sync(0xffffffffu, a3, 16);

    if (hf == 0) {
        size_t base = (size_t)gw * 64 + sub * 4;
        float d2 = g_dinv2[gw];
        float q0, q1, q2, q3;
        if (n == 1) {
            q0 = d2 * a0; q1 = d2 * a1; q2 = d2 * a2; q3 = d2 * a3;
        } else {
            uint2 oldu = *(const uint2*)(Qout + base);   // holds Q_{n-2}
            float2 o0 = __half22float2(*(half2*)&oldu.x);
            float2 o1 = __half22float2(*(half2*)&oldu.y);
            float s2x = 2.0f * d2;
            q0 = fmaf(s2x, a0, -o0.x);
            q1 = fmaf(s2x, a1, -o0.y);
            q2 = fmaf(s2x, a2, -o1.x);
            q3 = fmaf(s2x, a3, -o1.y);
        }
        if (!LAST) {
            uint2 outw;
            *(half2*)&outw.x = __floats2half2_rn(q0, q1);
            *(half2*)&outw.y = __floats2half2_rn(q2, q3);
            *(uint2*)(Qout + base) = outw;
        }

        float coef = __ldg(&lap[n - 1]);
        float4 mfv = *(const float4*)(mfw + (size_t)n * CD + sub * 4);
        float4 r = *(float4*)(g_ret + base);
        r.x = fmaf(coef * mfv.x, q0, r.x);
        r.y = fmaf(coef * mfv.y, q1, r.y);
        r.z = fmaf(coef * mfv.z, q2, r.z);
        r.w = fmaf(coef * mfv.w, q3, r.w);
        if (!LAST) {
            *(float4*)(g_ret + base) = r;
        } else {
            // fused final: scale by isq, log_softmax over 64 channels (lanes 0-15)
            float isq = g_isq[gw];
            r.x *= isq; r.y *= isq; r.z *= isq; r.w *= isq;
            float m = fmaxf(fmaxf(r.x, r.y), fmaxf(r.z, r.w));
            #pragma unroll
            for (int d = 8; d > 0; d >>= 1)
                m = fmaxf(m, __shfl_xor_sync(0x0000ffffu, m, d));
            float s = expf(r.x - m) + expf(r.y - m) + expf(r.z - m) + expf(r.w - m);
            #pragma unroll
            for (int d = 8; d > 0; d >>= 1)
                s += __shfl_xor_sync(0x0000ffffu, s, d);
            float lse = m + logf(s);
            float4 o = make_float4(r.x - lse, r.y - lse, r.z - lse, r.w - lse);
            *(float4*)(out + base) = o;
        }
    }
}

// ---------------- launch ----------------
extern "C" void kernel_launch(void* const* d_in, const int* in_sizes, int n_in,
                              void* d_out, int out_size) {
    const float* x   = (const float*)d_in[0];
    const void*  ei  = d_in[1];
    const float* W   = (const float*)d_in[2];
    const float* b   = (const float*)d_in[3];
    const float* lap = (const float*)d_in[4];
    const float* mf  = (const float*)d_in[5];
    float*       out = (float*)d_out;

    k_probe_zero<<<(NN + 255) / 256, 256>>>(ei);
    k_deg<<<(NE / 2 + 255) / 256, 256>>>(ei);
    k_scan1<<<NBLK, 1024>>>();
    k_scan2<<<1, 128>>>();
    k_scan3<<<(NN + 255) / 256, 256>>>();
    k_scatter<<<NE / 256, 256>>>(ei);
    k_gemm_tc<<<(NN + 127) / 128, 256>>>(x, W, b, mf);
    for (int n = 1; n < KORD; n++)
        k_prop<0><<<(NN * 32) / 256, 256>>>(n, lap, mf, out);
    k_prop<1><<<(NN * 32) / 256, 256>>>(KORD, lap, mf, out);
}